// round 13
// baseline (speedup 1.0000x reference)
#include <cuda_runtime.h>
#include <cuda_fp16.h>
#include <mma.h>
#include <math.h>
#include <stdint.h>

using namespace nvcuda;

#define Bb 8
#define Tt 1024
#define Dd 512
#define Hh 8
#define HD 64
#define D4 2048
#define ROWS (Bb*Tt)

// ---------------- scratch (device globals) ----------------
__device__ __half g_xn  [ROWS*Dd];
__device__ __half g_Qb  [Bb*Hh*Tt*64];
__device__ __half g_Kb  [Bb*Hh*Tt*64];
__device__ __half g_Vb  [Bb*Hh*Tt*64];
__device__ __half g_ctx [ROWS*Dd];
__device__ __half g_stdo[ROWS*Dd];
__device__ float  g_G   [Bb*64*64*512];
__device__ float  g_T1  [Bb*64*64*512];
__device__ float  g_cnt [Bb*4096];
__device__ float  g_dcnt[Bb*4096];
__device__ float  g_Av  [4096];
__device__ float  g_x1  [ROWS*Dd];
__device__ __half g_xn2 [ROWS*Dd];
__device__ __half g_hB  [ROWS*D4];
__device__ __half g_wIN [3*Dd*Dd];
__device__ __half g_wOUT[Dd*Dd];
__device__ __half g_w1  [D4*Dd];
__device__ __half g_w2  [Dd*D4];

// ---------------- helpers ----------------
__device__ __forceinline__ uint32_t smem_u32(const void* p) {
    uint32_t a;
    asm("{ .reg .u64 t; cvta.to.shared.u64 t, %1; cvt.u32.u64 %0, t; }" : "=r"(a) : "l"(p));
    return a;
}
__device__ __forceinline__ void cp16(uint32_t sdst, const void* gsrc) {
    asm volatile("cp.async.cg.shared.global [%0], [%1], 16;" :: "r"(sdst), "l"(gsrc));
}
__device__ __forceinline__ void cp_commit() {
    asm volatile("cp.async.commit_group;" ::: "memory");
}
template<int N>
__device__ __forceinline__ void cp_wait() {
    asm volatile("cp.async.wait_group %0;" :: "n"(N) : "memory");
}
__device__ __forceinline__ uint2 cvt4_h(float4 v) {
    __half2 a = __floats2half2_rn(v.x, v.y);
    __half2 b = __floats2half2_rn(v.z, v.w);
    uint2 r; r.x = *(unsigned*)&a; r.y = *(unsigned*)&b; return r;
}
__device__ __forceinline__ float gelu_exact(float v) {
    return 0.5f * v * (1.0f + erff(v * 0.7071067811865476f));
}

// ---------------- mma / ldmatrix primitives ----------------
__device__ __forceinline__ void ldsm_x4(uint32_t& r0, uint32_t& r1, uint32_t& r2, uint32_t& r3, uint32_t a) {
    asm volatile("ldmatrix.sync.aligned.m8n8.x4.shared.b16 {%0,%1,%2,%3}, [%4];"
                 : "=r"(r0),"=r"(r1),"=r"(r2),"=r"(r3) : "r"(a));
}
__device__ __forceinline__ void ldsm_x2(uint32_t& r0, uint32_t& r1, uint32_t a) {
    asm volatile("ldmatrix.sync.aligned.m8n8.x2.shared.b16 {%0,%1}, [%2];"
                 : "=r"(r0),"=r"(r1) : "r"(a));
}
__device__ __forceinline__ void ldsm_x2t(uint32_t& r0, uint32_t& r1, uint32_t a) {
    asm volatile("ldmatrix.sync.aligned.m8n8.x2.trans.shared.b16 {%0,%1}, [%2];"
                 : "=r"(r0),"=r"(r1) : "r"(a));
}
__device__ __forceinline__ void mma16816h(float* c, uint32_t a0, uint32_t a1, uint32_t a2, uint32_t a3,
                                          uint32_t b0, uint32_t b1) {
    asm volatile("mma.sync.aligned.m16n8k16.row.col.f32.f16.f16.f32 "
                 "{%0,%1,%2,%3}, {%4,%5,%6,%7}, {%8,%9}, {%0,%1,%2,%3};"
                 : "+f"(c[0]),"+f"(c[1]),"+f"(c[2]),"+f"(c[3])
                 : "r"(a0),"r"(a1),"r"(a2),"r"(a3),"r"(b0),"r"(b1));
}

// ---------------- zero kernel ----------------
__global__ __launch_bounds__(256) void zero_kernel(float* __restrict__ p, int n4) {
    int i = blockIdx.x * 256 + threadIdx.x;
    if (i < n4) *(float4*)&p[i*4] = make_float4(0.f,0.f,0.f,0.f);
}

// ---------------- weight conversion ----------------
__global__ __launch_bounds__(256) void conv_w_kernel(
    const float* __restrict__ W, __half* __restrict__ Wp, int total4)
{
    int idx = blockIdx.x * 256 + threadIdx.x;
    if (idx >= total4) return;
    float4 v = *(const float4*)&W[(long)idx * 4];
    *(uint2*)&Wp[(long)idx * 4] = cvt4_h(v);
}

// ================ plain fp16 GEMM ================
// EPI: 0 fp32+bias, 1 bias+gelu->fp16, 2 fp32+bias+residual, 3 QKV writer, 4 bias->fp16
#define GSTAGES 3
#define ASTR 40
#define ASZ   (128*ASTR*2)

template<int NT, int EPI>
__global__ __launch_bounds__(256) void gemm_fp16(
    const __half* __restrict__ A, const __half* __restrict__ B,
    const float* __restrict__ bias, const float* __restrict__ res,
    void* __restrict__ Cout, void* __restrict__ aux1, void* __restrict__ aux2,
    int N, int Kp)
{
    constexpr int NFR = NT/64;
    constexpr int BSZ = NT*ASTR*2;

    extern __shared__ __align__(128) char sm[];
    char* Abase = sm;
    char* Bbase = sm + GSTAGES * ASZ;

    const int tid = threadIdx.x;
    int w = tid >> 5, lane = tid & 31, wm = w >> 2, wn = w & 3;
    int m0 = blockIdx.y << 7, n0 = blockIdx.x * NT;

    int ar = tid >> 2, ac = (tid & 3) * 8;
    const __half* Ag = A + (long)(m0 + ar) * Kp + ac;
    const __half* Bg = B + (long)(n0 + ar) * Kp + ac;
    uint32_t Asw = smem_u32(Abase) + (uint32_t)(ar * (ASTR*2) + ac * 2);
    uint32_t Bsw = smem_u32(Bbase) + (uint32_t)(ar * (ASTR*2) + ac * 2);

    int nk = Kp >> 5;

#define GISSUE(kt) do { \
        if ((kt) < nk) { \
            int st_ = (kt) % GSTAGES; \
            long ko_ = (long)(kt) * 32; \
            uint32_t ad = Asw + (uint32_t)st_ * ASZ; \
            cp16(ad,                Ag + ko_); \
            cp16(ad + 64*(ASTR*2),  Ag + ko_ + (long)64*Kp); \
            uint32_t bd = Bsw + (uint32_t)st_ * BSZ; \
            _Pragma("unroll") \
            for (int i_ = 0; i_ < NT/64; i_++) \
                cp16(bd + i_*64*(ASTR*2), Bg + ko_ + (long)(i_*64)*Kp); \
        } \
        cp_commit(); \
    } while (0)

    wmma::fragment<wmma::accumulator, 16, 16, 16, float> acc[4][NFR];
#pragma unroll
    for (int i = 0; i < 4; i++)
#pragma unroll
        for (int j = 0; j < NFR; j++) wmma::fill_fragment(acc[i][j], 0.f);

#pragma unroll
    for (int i = 0; i < GSTAGES - 1; i++) GISSUE(i);

    for (int kt = 0; kt < nk; kt++) {
        cp_wait<GSTAGES - 2>();
        __syncthreads();
        GISSUE(kt + GSTAGES - 1);
        int st = kt % GSTAGES;
        const __half* Asm = (const __half*)(Abase + st * ASZ);
        const __half* Bsm = (const __half*)(Bbase + st * BSZ);
#pragma unroll
        for (int kk = 0; kk < 2; kk++) {
            wmma::fragment<wmma::matrix_a, 16, 16, 16, __half, wmma::row_major> af[4];
#pragma unroll
            for (int i = 0; i < 4; i++)
                wmma::load_matrix_sync(af[i], Asm + (wm*64 + i*16)*ASTR + kk*16, ASTR);
#pragma unroll
            for (int jh = 0; jh < NFR/2; jh++) {
                wmma::fragment<wmma::matrix_b, 16, 16, 16, __half, wmma::col_major> bf[2];
#pragma unroll
                for (int j = 0; j < 2; j++)
                    wmma::load_matrix_sync(bf[j], Bsm + (wn*(NT/4) + jh*32 + j*16)*ASTR + kk*16, ASTR);
#pragma unroll
                for (int i = 0; i < 4; i++)
#pragma unroll
                    for (int j = 0; j < 2; j++)
                        wmma::mma_sync(acc[i][jh*2+j], af[i], bf[j], acc[i][jh*2+j]);
            }
        }
    }
#undef GISSUE
    __syncthreads();   // before smem-reusing epilogue

    float* EP = (float*)sm + w * 256;
    int r = lane >> 1, c0 = (lane & 1) * 8;
#pragma unroll
    for (int i = 0; i < 4; i++) {
#pragma unroll
        for (int j = 0; j < NFR; j++) {
            wmma::store_matrix_sync(EP, acc[i][j], 16, wmma::mem_row_major);
            __syncwarp();
            long grow = m0 + wm*64 + i*16 + r;
            int  gcol = n0 + wn*(NT/4) + j*16 + c0;
            float4 v0 = *(float4*)&EP[r*16 + c0];
            float4 v1 = *(float4*)&EP[r*16 + c0 + 4];
            if (bias) {
                float4 b0 = *(const float4*)&bias[gcol];
                float4 b1 = *(const float4*)&bias[gcol + 4];
                v0.x += b0.x; v0.y += b0.y; v0.z += b0.z; v0.w += b0.w;
                v1.x += b1.x; v1.y += b1.y; v1.z += b1.z; v1.w += b1.w;
            }
            if (EPI == 1 || EPI == 4) {
                if (EPI == 1) {
                    v0.x = gelu_exact(v0.x); v0.y = gelu_exact(v0.y);
                    v0.z = gelu_exact(v0.z); v0.w = gelu_exact(v0.w);
                    v1.x = gelu_exact(v1.x); v1.y = gelu_exact(v1.y);
                    v1.z = gelu_exact(v1.z); v1.w = gelu_exact(v1.w);
                }
                uint2 H0 = cvt4_h(v0), H1 = cvt4_h(v1);
                *(uint4*)((__half*)Cout + grow * N + gcol) = make_uint4(H0.x,H0.y,H1.x,H1.y);
            } else if (EPI == 3) {
                int bidx = (int)(grow >> 10), t = (int)(grow & 1023);
                int sec = gcol >> 9, cc = gcol & 511, h = cc >> 6, d = cc & 63;
                long hrow = ((long)bidx*Hh + h)*Tt + t;
                if (sec == 0) {
                    v0.x *= 0.125f; v0.y *= 0.125f; v0.z *= 0.125f; v0.w *= 0.125f;
                    v1.x *= 0.125f; v1.y *= 0.125f; v1.z *= 0.125f; v1.w *= 0.125f;
                    uint2 H0 = cvt4_h(v0), H1 = cvt4_h(v1);
                    *(uint4*)((__half*)Cout + hrow*64 + d) = make_uint4(H0.x,H0.y,H1.x,H1.y);
                } else if (sec == 1) {
                    uint2 H0 = cvt4_h(v0), H1 = cvt4_h(v1);
                    *(uint4*)((__half*)aux1 + hrow*64 + d) = make_uint4(H0.x,H0.y,H1.x,H1.y);
                } else {
                    uint2 H0 = cvt4_h(v0), H1 = cvt4_h(v1);
                    *(uint4*)((__half*)aux2 + hrow*64 + d) = make_uint4(H0.x,H0.y,H1.x,H1.y);
                }
            } else {
                float* C = (float*)Cout;
                if (EPI == 2) {
                    float4 r0 = *(const float4*)&res[grow*N + gcol];
                    float4 r1 = *(const float4*)&res[grow*N + gcol + 4];
                    v0.x += r0.x; v0.y += r0.y; v0.z += r0.z; v0.w += r0.w;
                    v1.x += r1.x; v1.y += r1.y; v1.z += r1.z; v1.w += r1.w;
                }
                *(float4*)&C[grow*(long)N + gcol]     = v0;
                *(float4*)&C[grow*(long)N + gcol + 4] = v1;
            }
            __syncwarp();
        }
    }
}

#define GSMEM_W256 (GSTAGES*(ASZ + 256*ASTR*2))
#define GSMEM_W128 (GSTAGES*(ASZ + 128*ASTR*2))

// ---------------- LN1 ----------------
__global__ __launch_bounds__(256) void ln1_kernel(
    const float* __restrict__ x, const float* __restrict__ w,
    const float* __restrict__ b, __half* __restrict__ xn)
{
    int warp = threadIdx.x >> 5, lane = threadIdx.x & 31;
    long row = (long)blockIdx.x * 8 + warp;
    const float* xr = x + row * Dd;
    float4 v[4];
    float s = 0.f, sq = 0.f;
#pragma unroll
    for (int i = 0; i < 4; i++) {
        v[i] = *(const float4*)&xr[lane*4 + i*128];
        s  += v[i].x + v[i].y + v[i].z + v[i].w;
        sq += v[i].x*v[i].x + v[i].y*v[i].y + v[i].z*v[i].z + v[i].w*v[i].w;
    }
#pragma unroll
    for (int o = 16; o; o >>= 1) {
        s  += __shfl_xor_sync(0xffffffffu, s,  o);
        sq += __shfl_xor_sync(0xffffffffu, sq, o);
    }
    float mean = s * (1.0f/512.0f);
    float var  = sq * (1.0f/512.0f) - mean*mean;
    float rr   = rsqrtf(var + 1e-5f);
    __half* yr = xn + row * Dd;
#pragma unroll
    for (int i = 0; i < 4; i++) {
        int d = lane*4 + i*128;
        float4 wv = *(const float4*)&w[d];
        float4 bv = *(const float4*)&b[d];
        float4 o4;
        o4.x = (v[i].x - mean)*rr*wv.x + bv.x;
        o4.y = (v[i].y - mean)*rr*wv.y + bv.y;
        o4.z = (v[i].z - mean)*rr*wv.z + bv.z;
        o4.w = (v[i].w - mean)*rr*wv.w + bv.w;
        *(uint2*)&yr[d] = cvt4_h(o4);
    }
}

// ---------------- flash attention: 64-q tiles, 128 threads (round-11 shape) ----------------
#define QSTR 72
#define KBUF (64*QSTR)
#define ATTN_SMEM (5*KBUF*2)   // 46080 B

__global__ __launch_bounds__(128) void attn_mma_kernel(
    const __half* __restrict__ Qb, const __half* __restrict__ Kb,
    const __half* __restrict__ Vb, __half* __restrict__ ctx)
{
    extern __shared__ __half smh[];
    __half* Qs  = smh;
    __half* Ks0 = smh + KBUF;
    __half* Vs0 = smh + 3*KBUF;

    int b = blockIdx.z, h = blockIdx.y, qt = blockIdx.x;
    int tid = threadIdx.x, wq = tid >> 5, lane = tid & 31;
    long hbase = ((long)b*Hh + h)*Tt;

    const __half* Qg = Qb + (hbase + qt*64)*64;
    const __half* Kg = Kb + hbase*64;
    const __half* Vg = Vb + hbase*64;

    int lr = tid >> 1, lc = tid & 1;
    uint32_t QsA = smem_u32(Qs)  + lr*(QSTR*2) + lc*64;
    uint32_t KsA = smem_u32(Ks0) + lr*(QSTR*2) + lc*64;
    uint32_t VsA = smem_u32(Vs0) + lr*(QSTR*2) + lc*64;

#pragma unroll
    for (int i = 0; i < 4; i++)
        cp16(QsA + i*16, Qg + lr*64 + lc*32 + i*8);
#define ISSUE_KV(kt, buf) do { \
        const __half* kg_ = Kg + (long)((kt)*64 + lr)*64 + lc*32; \
        uint32_t kd_ = KsA + (buf)*(KBUF*2); \
        _Pragma("unroll") \
        for (int i_ = 0; i_ < 4; i_++) cp16(kd_ + i_*16, kg_ + i_*8); \
        const __half* vg_ = Vg + (long)((kt)*64 + lr)*64 + lc*32; \
        uint32_t vd_ = VsA + (buf)*(KBUF*2); \
        _Pragma("unroll") \
        for (int i_ = 0; i_ < 4; i_++) cp16(vd_ + i_*16, vg_ + i_*8); \
    } while (0)
    ISSUE_KV(0, 0);
    cp_commit();

    float cf[8][4];
#pragma unroll
    for (int j = 0; j < 8; j++) { cf[j][0]=0.f; cf[j][1]=0.f; cf[j][2]=0.f; cf[j][3]=0.f; }
    float m0 = -1e30f, m1 = -1e30f, l0 = 0.f, l1 = 0.f;

    uint32_t qaddr = smem_u32(&Qs[(16*wq + (lane & 15))*QSTR + 8*(lane >> 4)]);

    for (int kt = 0; kt < 16; kt++) {
        if (kt + 1 < 16) ISSUE_KV(kt + 1, (kt + 1) & 1);
        cp_commit();
        cp_wait<1>();
        __syncthreads();
        const __half* Kbuf = Ks0 + (kt & 1)*KBUF;
        const __half* Vbuf = Vs0 + (kt & 1)*KBUF;

        float sf[8][4] = {};
#pragma unroll
        for (int kc = 0; kc < 4; kc++) {
            uint32_t a0, a1, a2, a3;
            ldsm_x4(a0, a1, a2, a3, qaddr + kc*32);
#pragma unroll
            for (int n8 = 0; n8 < 8; n8++) {
                uint32_t b0, b1;
                uint32_t ka = smem_u32(&Kbuf[(8*n8 + (lane & 7))*QSTR + 16*kc + 8*((lane >> 3) & 1)]);
                ldsm_x2(b0, b1, ka);
                mma16816h(sf[n8], a0, a1, a2, a3, b0, b1);
            }
        }

        float mt0 = -1e30f, mt1 = -1e30f;
#pragma unroll
        for (int j = 0; j < 8; j++) {
            mt0 = fmaxf(mt0, fmaxf(sf[j][0], sf[j][1]));
            mt1 = fmaxf(mt1, fmaxf(sf[j][2], sf[j][3]));
        }
        mt0 = fmaxf(mt0, __shfl_xor_sync(0xffffffffu, mt0, 1));
        mt0 = fmaxf(mt0, __shfl_xor_sync(0xffffffffu, mt0, 2));
        mt1 = fmaxf(mt1, __shfl_xor_sync(0xffffffffu, mt1, 1));
        mt1 = fmaxf(mt1, __shfl_xor_sync(0xffffffffu, mt1, 2));
        float mn0 = fmaxf(m0, mt0), mn1 = fmaxf(m1, mt1);
        float cr0 = __expf(m0 - mn0), cr1 = __expf(m1 - mn1);
        m0 = mn0; m1 = mn1; l0 *= cr0; l1 *= cr1;
#pragma unroll
        for (int j = 0; j < 8; j++) {
            cf[j][0] *= cr0; cf[j][1] *= cr0; cf[j][2] *= cr1; cf[j][3] *= cr1;
        }

        uint32_t pa[4][4];
#pragma unroll
        for (int jk = 0; jk < 4; jk++) {
            float e00 = __expf(sf[2*jk][0]   - mn0), e01 = __expf(sf[2*jk][1]   - mn0);
            float e10 = __expf(sf[2*jk][2]   - mn1), e11 = __expf(sf[2*jk][3]   - mn1);
            float e20 = __expf(sf[2*jk+1][0] - mn0), e21 = __expf(sf[2*jk+1][1] - mn0);
            float e30 = __expf(sf[2*jk+1][2] - mn1), e31 = __expf(sf[2*jk+1][3] - mn1);
            l0 += e00 + e01 + e20 + e21;
            l1 += e10 + e11 + e30 + e31;
            __half2 t;
            t = __floats2half2_rn(e00, e01); pa[jk][0] = *(unsigned*)&t;
            t = __floats2half2_rn(e10, e11); pa[jk][1] = *(unsigned*)&t;
            t = __floats2half2_rn(e20, e21); pa[jk][2] = *(unsigned*)&t;
            t = __floats2half2_rn(e30, e31); pa[jk][3] = *(unsigned*)&t;
        }

#pragma unroll
        for (int jk = 0; jk < 4; jk++) {
#pragma unroll
            for (int jd = 0; jd < 8; jd++) {
                uint32_t b0, b1;
                uint32_t va = smem_u32(&Vbuf[(16*jk + (lane & 15))*QSTR + 8*jd]);
                ldsm_x2t(b0, b1, va);
                mma16816h(cf[jd], pa[jk][0], pa[jk][1], pa[jk][2], pa[jk][3], b0, b1);
            }
        }
        __syncthreads();
    }
#undef ISSUE_KV

    l0 += __shfl_xor_sync(0xffffffffu, l0, 1);
    l0 += __shfl_xor_sync(0xffffffffu, l0, 2);
    l1 += __shfl_xor_sync(0xffffffffu, l1, 1);
    l1 += __shfl_xor_sync(0xffffffffu, l1, 2);
    float inv0 = 1.0f / l0, inv1 = 1.0f / l1;

    long grow0 = (long)b*Tt + qt*64 + 16*wq + (lane >> 2);
    long grow1 = grow0 + 8;
    int colb = h*HD + 2*(lane & 3);
    __half* cr0p = ctx + grow0 * Dd;
    __half* cr1p = ctx + grow1 * Dd;
#pragma unroll
    for (int jd = 0; jd < 8; jd++) {
        int col = colb + 8*jd;
        {
            __half2 Hp = __floats2half2_rn(cf[jd][0]*inv0, cf[jd][1]*inv0);
            *(unsigned*)&cr0p[col] = *(unsigned*)&Hp;
        }
        {
            __half2 Hp = __floats2half2_rn(cf[jd][2]*inv1, cf[jd][3]*inv1);
            *(unsigned*)&cr1p[col] = *(unsigned*)&Hp;
        }
    }
}

// ---------------- separable Gaussian position attention ----------------
__global__ __launch_bounds__(256) void av_init_kernel(float* __restrict__ Av) {
    int i = blockIdx.x * 256 + threadIdx.x;
    float d = (float)((i >> 6) - (i & 63));
    Av[i] = __expf(-d * d * (1.0f/512.0f));
}

__global__ __launch_bounds__(256) void scatter_kernel(
    const __half* __restrict__ xn, const int* __restrict__ posv,
    const int* __restrict__ posh, float* __restrict__ G, float* __restrict__ cnt)
{
    int warp = threadIdx.x >> 5, lane = threadIdx.x & 31;
    long row = (long)blockIdx.x * 8 + warp;
    int b = (int)(row >> 10), t = (int)(row & 1023);
    int pv = posv[b*Tt + t], ph = posh[b*Tt + t];
    float* dst = G + (((long)b*64 + pv)*64 + ph) * 512;
    const __half* ar = xn + row * Dd;
#pragma unroll
    for (int i = 0; i < 16; i++) {
        int d = i*32 + lane;
        atomicAdd(&dst[d], __half2float(ar[d]));
    }
    if (lane == 0) atomicAdd(&cnt[((long)b*64 + pv)*64 + ph], 1.0f);
}

__global__ __launch_bounds__(512) void gconv_kernel(
    const float* __restrict__ in, float* __restrict__ out,
    const float* __restrict__ Av, int stride_fix, int stride_c)
{
    __shared__ float AsT[64][64];
    int fix = blockIdx.x, b = blockIdx.y, tid = threadIdx.x;
    for (int i = tid; i < 4096; i += 512)
        AsT[i & 63][i >> 6] = Av[i];
    __syncthreads();
    const float* ib = in  + (long)b*2097152 + (long)fix*stride_fix + tid;
    float* ob       = out + (long)b*2097152 + (long)fix*stride_fix + tid;
    float acc[64];
#pragma unroll
    for (int v = 0; v < 64; v++) acc[v] = 0.f;
    for (int c = 0; c < 64; c++) {
        float g = ib[(long)c * stride_c];
#pragma unroll
        for (int v4 = 0; v4 < 16; v4++) {
            float4 a4 = *(const float4*)&AsT[c][v4*4];
            acc[v4*4+0] += a4.x*g; acc[v4*4+1] += a4.y*g;
            acc[v4*4+2] += a4.z*g; acc[v4*4+3] += a4.w*g;
        }
    }
#pragma unroll
    for (int v = 0; v < 64; v++) ob[(long)v * stride_c] = acc[v];
}

__global__ __launch_bounds__(1024) void dcnt_kernel(
    const float* __restrict__ cnt, const float* __restrict__ Av,
    float* __restrict__ dcnt)
{
    __shared__ float sc[4096], st[4096];
    int b = blockIdx.x, tid = threadIdx.x;
    for (int i = tid; i < 4096; i += 1024) sc[i] = cnt[(long)b*4096 + i];
    __syncthreads();
    for (int i = tid; i < 4096; i += 1024) {
        int v = i >> 6, hp = i & 63;
        float s = 0.f;
        for (int vp = 0; vp < 64; vp++) s += Av[v*64+vp] * sc[vp*64+hp];
        st[i] = s;
    }
    __syncthreads();
    for (int i = tid; i < 4096; i += 1024) {
        int v = i >> 6, h = i & 63;
        float s = 0.f;
        for (int hp = 0; hp < 64; hp++) s += Av[h*64+hp] * st[v*64+hp];
        dcnt[(long)b*4096 + i] = 1.0f / s;
    }
}

// ---------------- combine + LN2 (stdo in fp16) ----------------
__global__ __launch_bounds__(256) void combine_ln2_kernel(
    const float* __restrict__ x, const __half* __restrict__ stdo,
    const float* __restrict__ O, const float* __restrict__ dcntInv,
    const int* __restrict__ posv, const int* __restrict__ posh,
    const float* __restrict__ gate,
    const float* __restrict__ w, const float* __restrict__ bb,
    float* __restrict__ x1, __half* __restrict__ xn2)
{
    int warp = threadIdx.x >> 5, lane = threadIdx.x & 31;
    long row = (long)blockIdx.x * 8 + warp;
    int b = (int)(row >> 10), t = (int)(row & 1023);
    int pv = posv[b*Tt + t], ph = posh[b*Tt + t];
    float g = 1.0f / (1.0f + __expf(-gate[0]));
    float gi = 1.0f - g;
    float inv_ks = dcntInv[((long)b*64 + pv)*64 + ph];
    const float* korow = O + (((long)b*64 + pv)*64 + ph) * 512;
    long base = row * Dd;
    float4 v[4];
    float s = 0.f, sq = 0.f;
#pragma unroll
    for (int i = 0; i < 4; i++) {
        int d = lane*4 + i*128;
        float4 xv = *(const float4*)&x[base + d];
        uint2 su = *(const uint2*)&stdo[base + d];
        float2 s01 = __half22float2(*(const __half2*)&su.x);
        float2 s23 = __half22float2(*(const __half2*)&su.y);
        float4 kv = *(const float4*)&korow[d];
        float4 o4;
        o4.x = xv.x + g*s01.x + gi*kv.x*inv_ks;
        o4.y = xv.y + g*s01.y + gi*kv.y*inv_ks;
        o4.z = xv.z + g*s23.x + gi*kv.z*inv_ks;
        o4.w = xv.w + g*s23.y + gi*kv.w*inv_ks;
        *(float4*)&x1[base + d] = o4;
        v[i] = o4;
        s  += o4.x + o4.y + o4.z + o4.w;
        sq += o4.x*o4.x + o4.y*o4.y + o4.z*o4.z + o4.w*o4.w;
    }
#pragma unroll
    for (int o = 16; o; o >>= 1) {
        s  += __shfl_xor_sync(0xffffffffu, s,  o);
        sq += __shfl_xor_sync(0xffffffffu, sq, o);
    }
    float mean = s * (1.0f/512.0f);
    float var  = sq * (1.0f/512.0f) - mean*mean;
    float rr   = rsqrtf(var + 1e-5f);
    __half* arow = xn2 + row * Dd;
#pragma unroll
    for (int i = 0; i < 4; i++) {
        int d = lane*4 + i*128;
        float4 wv = *(const float4*)&w[d];
        float4 bv = *(const float4*)&bb[d];
        float4 o4;
        o4.x = (v[i].x - mean)*rr*wv.x + bv.x;
        o4.y = (v[i].y - mean)*rr*wv.y + bv.y;
        o4.z = (v[i].z - mean)*rr*wv.z + bv.z;
        o4.w = (v[i].w - mean)*rr*wv.w + bv.w;
        *(uint2*)&arow[d] = cvt4_h(o4);
    }
}

// ---------------- launch ----------------
extern "C" void kernel_launch(void* const* d_in, const int* in_sizes, int n_in,
                              void* d_out, int out_size)
{
    const float* x      = (const float*)d_in[0];
    const int*   posv   = (const int*)  d_in[1];
    const int*   posh   = (const int*)  d_in[2];
    const float* n1w    = (const float*)d_in[3];
    const float* n1b    = (const float*)d_in[4];
    const float* in_w   = (const float*)d_in[5];
    const float* in_b   = (const float*)d_in[6];
    const float* out_w  = (const float*)d_in[7];
    const float* out_b  = (const float*)d_in[8];
    const float* n2w    = (const float*)d_in[9];
    const float* n2b    = (const float*)d_in[10];
    const float* w1     = (const float*)d_in[11];
    const float* b1     = (const float*)d_in[12];
    const float* w2     = (const float*)d_in[13];
    const float* b2     = (const float*)d_in[14];
    const float* gate   = (const float*)d_in[15];
    float* out = (float*)d_out;

    __half *xn, *ctx, *stdo, *xn2, *hB, *wIN, *wOUT, *w1p, *w2p, *Qbp, *Kbp, *Vbp;
    float *G, *T1, *cnt, *dcnt, *Av, *x1;
    cudaGetSymbolAddress((void**)&xn,   g_xn);
    cudaGetSymbolAddress((void**)&Qbp,  g_Qb);
    cudaGetSymbolAddress((void**)&Kbp,  g_Kb);
    cudaGetSymbolAddress((void**)&Vbp,  g_Vb);
    cudaGetSymbolAddress((void**)&ctx,  g_ctx);
    cudaGetSymbolAddress((void**)&stdo, g_stdo);
    cudaGetSymbolAddress((void**)&G,    g_G);
    cudaGetSymbolAddress((void**)&T1,   g_T1);
    cudaGetSymbolAddress((void**)&cnt,  g_cnt);
    cudaGetSymbolAddress((void**)&dcnt, g_dcnt);
    cudaGetSymbolAddress((void**)&Av,   g_Av);
    cudaGetSymbolAddress((void**)&x1,   g_x1);
    cudaGetSymbolAddress((void**)&xn2,  g_xn2);
    cudaGetSymbolAddress((void**)&hB,   g_hB);
    cudaGetSymbolAddress((void**)&wIN,  g_wIN);
    cudaGetSymbolAddress((void**)&wOUT, g_wOUT);
    cudaGetSymbolAddress((void**)&w1p,  g_w1);
    cudaGetSymbolAddress((void**)&w2p,  g_w2);

    cudaFuncSetAttribute(gemm_fp16<256,3>, cudaFuncAttributeMaxDynamicSharedMemorySize, GSMEM_W256);
    cudaFuncSetAttribute(gemm_fp16<256,1>, cudaFuncAttributeMaxDynamicSharedMemorySize, GSMEM_W256);
    cudaFuncSetAttribute(gemm_fp16<128,4>, cudaFuncAttributeMaxDynamicSharedMemorySize, GSMEM_W128);
    cudaFuncSetAttribute(gemm_fp16<128,2>, cudaFuncAttributeMaxDynamicSharedMemorySize, GSMEM_W128);
    cudaFuncSetAttribute(attn_mma_kernel,  cudaFuncAttributeMaxDynamicSharedMemorySize, ATTN_SMEM);

    // side stream fork
    cudaStream_t sA;
    cudaStreamCreateWithFlags(&sA, cudaStreamNonBlocking);
    cudaEvent_t evRoot, evWIN, evW, evLN, evG;
    cudaEventCreateWithFlags(&evRoot, cudaEventDisableTiming);
    cudaEventCreateWithFlags(&evWIN, cudaEventDisableTiming);
    cudaEventCreateWithFlags(&evW,   cudaEventDisableTiming);
    cudaEventCreateWithFlags(&evLN,  cudaEventDisableTiming);
    cudaEventCreateWithFlags(&evG,   cudaEventDisableTiming);

    cudaEventRecord(evRoot, 0);
    cudaStreamWaitEvent(sA, evRoot, 0);

    // side: wIN first (QKV gate), then remaining weights, Av, zeros
    conv_w_kernel<<<(3*Dd*Dd/4 + 255)/256, 256, 0, sA>>>(in_w, wIN, 3*Dd*Dd/4);
    cudaEventRecord(evWIN, sA);
    conv_w_kernel<<<(Dd*Dd/4 + 255)/256, 256, 0, sA>>>(out_w, wOUT, Dd*Dd/4);
    conv_w_kernel<<<(D4*Dd/4 + 255)/256, 256, 0, sA>>>(w1,    w1p,  D4*Dd/4);
    conv_w_kernel<<<(Dd*D4/4 + 255)/256, 256, 0, sA>>>(w2,    w2p,  Dd*D4/4);
    cudaEventRecord(evW, sA);
    av_init_kernel<<<16, 256, 0, sA>>>(Av);
    zero_kernel<<<(Bb*4096*512/4 + 255)/256, 256, 0, sA>>>(G, Bb*4096*512/4);
    zero_kernel<<<(Bb*4096/4 + 255)/256, 256, 0, sA>>>(cnt, Bb*4096/4);

    // main: LN1 (concurrent with conv_wIN)
    ln1_kernel<<<ROWS/8, 256>>>(x, n1w, n1b, xn);
    cudaEventRecord(evLN, 0);

    // side: Gaussian path
    cudaStreamWaitEvent(sA, evLN, 0);
    scatter_kernel<<<ROWS/8, 256, 0, sA>>>(xn, posv, posh, G, cnt);
    gconv_kernel<<<dim3(64, Bb), 512, 0, sA>>>(G, T1, Av, 512, 64*512);
    gconv_kernel<<<dim3(64, Bb), 512, 0, sA>>>(T1, G, Av, 64*512, 512);
    dcnt_kernel<<<Bb, 1024, 0, sA>>>(cnt, Av, dcnt);
    cudaEventRecord(evG, sA);

    // main: QKV GEMM (needs wIN)
    cudaStreamWaitEvent(0, evWIN, 0);
    gemm_fp16<256, 3><<<dim3(6, 64), 256, GSMEM_W256>>>(
        xn, wIN, in_b, nullptr, Qbp, Kbp, Vbp, 3*Dd, Dd);

    // main: attention (64-q tiles, round-11 shape)
    attn_mma_kernel<<<dim3(Tt/64, Hh, Bb), 128, ATTN_SMEM>>>(Qbp, Kbp, Vbp, ctx);

    // main: out-proj -> fp16 stdo
    cudaStreamWaitEvent(0, evW, 0);
    gemm_fp16<128, 4><<<dim3(4, 64), 256, GSMEM_W128>>>(
        ctx, wOUT, out_b, nullptr, stdo, nullptr, nullptr, Dd, Dd);

    // main: combine + LN2
    cudaStreamWaitEvent(0, evG, 0);
    combine_ln2_kernel<<<ROWS/8, 256>>>(
        x, stdo, G, dcnt, posv, posh, gate, n2w, n2b, x1, xn2);

    // main: MLP
    gemm_fp16<256, 1><<<dim3(8, 64), 256, GSMEM_W256>>>(
        xn2, w1p, b1, nullptr, hB, nullptr, nullptr, D4, Dd);
    gemm_fp16<128, 2><<<dim3(4, 64), 256, GSMEM_W128>>>(
        hB, w2p, b2, x1, out, nullptr, nullptr, Dd, D4);
}

// round 14
// speedup vs baseline: 1.0881x; 1.0881x over previous
#include <cuda_runtime.h>
#include <cuda_fp16.h>
#include <mma.h>
#include <math.h>
#include <stdint.h>

using namespace nvcuda;

#define Bb 8
#define Tt 1024
#define Dd 512
#define Hh 8
#define HD 64
#define D4 2048
#define ROWS (Bb*Tt)

// ---------------- scratch (device globals) ----------------
__device__ __half g_xn  [ROWS*Dd];
__device__ __half g_Qb  [Bb*Hh*Tt*64];
__device__ __half g_Kb  [Bb*Hh*Tt*64];
__device__ __half g_Vb  [Bb*Hh*Tt*64];
__device__ __half g_ctx [ROWS*Dd];
__device__ __half g_stdo[ROWS*Dd];
__device__ float  g_G   [Bb*64*64*512];
__device__ float  g_T1  [Bb*64*64*512];
__device__ float  g_cnt [Bb*4096];
__device__ float  g_dcnt[Bb*4096];
__device__ float  g_Av  [4096];
__device__ float  g_x1  [ROWS*Dd];
__device__ __half g_xn2 [ROWS*Dd];
__device__ __half g_hB  [ROWS*D4];
__device__ __half g_wIN [3*Dd*Dd];
__device__ __half g_wOUT[Dd*Dd];
__device__ __half g_w1  [D4*Dd];
__device__ __half g_w2  [Dd*D4];

// ---------------- helpers ----------------
__device__ __forceinline__ uint32_t smem_u32(const void* p) {
    uint32_t a;
    asm("{ .reg .u64 t; cvta.to.shared.u64 t, %1; cvt.u32.u64 %0, t; }" : "=r"(a) : "l"(p));
    return a;
}
__device__ __forceinline__ void cp16(uint32_t sdst, const void* gsrc) {
    asm volatile("cp.async.cg.shared.global [%0], [%1], 16;" :: "r"(sdst), "l"(gsrc));
}
__device__ __forceinline__ void cp_commit() {
    asm volatile("cp.async.commit_group;" ::: "memory");
}
template<int N>
__device__ __forceinline__ void cp_wait() {
    asm volatile("cp.async.wait_group %0;" :: "n"(N) : "memory");
}
__device__ __forceinline__ uint2 cvt4_h(float4 v) {
    __half2 a = __floats2half2_rn(v.x, v.y);
    __half2 b = __floats2half2_rn(v.z, v.w);
    uint2 r; r.x = *(unsigned*)&a; r.y = *(unsigned*)&b; return r;
}
__device__ __forceinline__ float gelu_exact(float v) {
    return 0.5f * v * (1.0f + erff(v * 0.7071067811865476f));
}

// ---------------- mma / ldmatrix primitives ----------------
__device__ __forceinline__ void ldsm_x4(uint32_t& r0, uint32_t& r1, uint32_t& r2, uint32_t& r3, uint32_t a) {
    asm volatile("ldmatrix.sync.aligned.m8n8.x4.shared.b16 {%0,%1,%2,%3}, [%4];"
                 : "=r"(r0),"=r"(r1),"=r"(r2),"=r"(r3) : "r"(a));
}
__device__ __forceinline__ void ldsm_x2(uint32_t& r0, uint32_t& r1, uint32_t a) {
    asm volatile("ldmatrix.sync.aligned.m8n8.x2.shared.b16 {%0,%1}, [%2];"
                 : "=r"(r0),"=r"(r1) : "r"(a));
}
__device__ __forceinline__ void ldsm_x2t(uint32_t& r0, uint32_t& r1, uint32_t a) {
    asm volatile("ldmatrix.sync.aligned.m8n8.x2.trans.shared.b16 {%0,%1}, [%2];"
                 : "=r"(r0),"=r"(r1) : "r"(a));
}
__device__ __forceinline__ void mma16816h(float* c, uint32_t a0, uint32_t a1, uint32_t a2, uint32_t a3,
                                          uint32_t b0, uint32_t b1) {
    asm volatile("mma.sync.aligned.m16n8k16.row.col.f32.f16.f16.f32 "
                 "{%0,%1,%2,%3}, {%4,%5,%6,%7}, {%8,%9}, {%0,%1,%2,%3};"
                 : "+f"(c[0]),"+f"(c[1]),"+f"(c[2]),"+f"(c[3])
                 : "r"(a0),"r"(a1),"r"(a2),"r"(a3),"r"(b0),"r"(b1));
}

// ---------------- zero kernel ----------------
__global__ __launch_bounds__(256) void zero_kernel(float* __restrict__ p, int n4) {
    int i = blockIdx.x * 256 + threadIdx.x;
    if (i < n4) *(float4*)&p[i*4] = make_float4(0.f,0.f,0.f,0.f);
}

// ---------------- weight conversion ----------------
__global__ __launch_bounds__(256) void conv_w_kernel(
    const float* __restrict__ W, __half* __restrict__ Wp, int total4)
{
    int idx = blockIdx.x * 256 + threadIdx.x;
    if (idx >= total4) return;
    float4 v = *(const float4*)&W[(long)idx * 4];
    *(uint2*)&Wp[(long)idx * 4] = cvt4_h(v);
}

// ================ plain fp16 GEMM (round-11 structure) ================
// EPI: 0 fp32+bias, 1 bias+gelu->fp16, 2 fp32+bias+residual, 3 QKV writer, 4 bias->fp16
#define GSTAGES 3
#define ASTR 40
#define ASZ   (128*ASTR*2)

template<int NT, int EPI>
__global__ __launch_bounds__(256) void gemm_fp16(
    const __half* __restrict__ A, const __half* __restrict__ B,
    const float* __restrict__ bias, const float* __restrict__ res,
    void* __restrict__ Cout, void* __restrict__ aux1, void* __restrict__ aux2,
    int N, int Kp)
{
    constexpr int NFR = NT/64;
    constexpr int BSZ = NT*ASTR*2;

    extern __shared__ __align__(128) char sm[];
    char* Abase = sm;
    char* Bbase = sm + GSTAGES * ASZ;

    const int tid = threadIdx.x;
    int w = tid >> 5, lane = tid & 31, wm = w >> 2, wn = w & 3;
    int m0 = blockIdx.y << 7, n0 = blockIdx.x * NT;

    int ar = tid >> 2, ac = (tid & 3) * 8;
    const __half* Ag = A + (long)(m0 + ar) * Kp + ac;
    const __half* Bg = B + (long)(n0 + ar) * Kp + ac;
    uint32_t Asw = smem_u32(Abase) + (uint32_t)(ar * (ASTR*2) + ac * 2);
    uint32_t Bsw = smem_u32(Bbase) + (uint32_t)(ar * (ASTR*2) + ac * 2);

    int nk = Kp >> 5;

#define GISSUE(kt) do { \
        if ((kt) < nk) { \
            int st_ = (kt) % GSTAGES; \
            long ko_ = (long)(kt) * 32; \
            uint32_t ad = Asw + (uint32_t)st_ * ASZ; \
            cp16(ad,                Ag + ko_); \
            cp16(ad + 64*(ASTR*2),  Ag + ko_ + (long)64*Kp); \
            uint32_t bd = Bsw + (uint32_t)st_ * BSZ; \
            _Pragma("unroll") \
            for (int i_ = 0; i_ < NT/64; i_++) \
                cp16(bd + i_*64*(ASTR*2), Bg + ko_ + (long)(i_*64)*Kp); \
        } \
        cp_commit(); \
    } while (0)

    wmma::fragment<wmma::accumulator, 16, 16, 16, float> acc[4][NFR];
#pragma unroll
    for (int i = 0; i < 4; i++)
#pragma unroll
        for (int j = 0; j < NFR; j++) wmma::fill_fragment(acc[i][j], 0.f);

#pragma unroll
    for (int i = 0; i < GSTAGES - 1; i++) GISSUE(i);

    for (int kt = 0; kt < nk; kt++) {
        cp_wait<GSTAGES - 2>();
        __syncthreads();
        GISSUE(kt + GSTAGES - 1);
        int st = kt % GSTAGES;
        const __half* Asm = (const __half*)(Abase + st * ASZ);
        const __half* Bsm = (const __half*)(Bbase + st * BSZ);
#pragma unroll
        for (int kk = 0; kk < 2; kk++) {
            wmma::fragment<wmma::matrix_a, 16, 16, 16, __half, wmma::row_major> af[4];
#pragma unroll
            for (int i = 0; i < 4; i++)
                wmma::load_matrix_sync(af[i], Asm + (wm*64 + i*16)*ASTR + kk*16, ASTR);
#pragma unroll
            for (int jh = 0; jh < NFR/2; jh++) {
                wmma::fragment<wmma::matrix_b, 16, 16, 16, __half, wmma::col_major> bf[2];
#pragma unroll
                for (int j = 0; j < 2; j++)
                    wmma::load_matrix_sync(bf[j], Bsm + (wn*(NT/4) + jh*32 + j*16)*ASTR + kk*16, ASTR);
#pragma unroll
                for (int i = 0; i < 4; i++)
#pragma unroll
                    for (int j = 0; j < 2; j++)
                        wmma::mma_sync(acc[i][jh*2+j], af[i], bf[j], acc[i][jh*2+j]);
            }
        }
        __syncthreads();
    }
#undef GISSUE

    float* EP = (float*)sm + w * 256;
    int r = lane >> 1, c0 = (lane & 1) * 8;
#pragma unroll
    for (int i = 0; i < 4; i++) {
#pragma unroll
        for (int j = 0; j < NFR; j++) {
            wmma::store_matrix_sync(EP, acc[i][j], 16, wmma::mem_row_major);
            __syncwarp();
            long grow = m0 + wm*64 + i*16 + r;
            int  gcol = n0 + wn*(NT/4) + j*16 + c0;
            float4 v0 = *(float4*)&EP[r*16 + c0];
            float4 v1 = *(float4*)&EP[r*16 + c0 + 4];
            if (bias) {
                float4 b0 = *(const float4*)&bias[gcol];
                float4 b1 = *(const float4*)&bias[gcol + 4];
                v0.x += b0.x; v0.y += b0.y; v0.z += b0.z; v0.w += b0.w;
                v1.x += b1.x; v1.y += b1.y; v1.z += b1.z; v1.w += b1.w;
            }
            if (EPI == 1 || EPI == 4) {
                if (EPI == 1) {
                    v0.x = gelu_exact(v0.x); v0.y = gelu_exact(v0.y);
                    v0.z = gelu_exact(v0.z); v0.w = gelu_exact(v0.w);
                    v1.x = gelu_exact(v1.x); v1.y = gelu_exact(v1.y);
                    v1.z = gelu_exact(v1.z); v1.w = gelu_exact(v1.w);
                }
                uint2 H0 = cvt4_h(v0), H1 = cvt4_h(v1);
                *(uint4*)((__half*)Cout + grow * N + gcol) = make_uint4(H0.x,H0.y,H1.x,H1.y);
            } else if (EPI == 3) {
                int bidx = (int)(grow >> 10), t = (int)(grow & 1023);
                int sec = gcol >> 9, cc = gcol & 511, h = cc >> 6, d = cc & 63;
                long hrow = ((long)bidx*Hh + h)*Tt + t;
                if (sec == 0) {
                    v0.x *= 0.125f; v0.y *= 0.125f; v0.z *= 0.125f; v0.w *= 0.125f;
                    v1.x *= 0.125f; v1.y *= 0.125f; v1.z *= 0.125f; v1.w *= 0.125f;
                    uint2 H0 = cvt4_h(v0), H1 = cvt4_h(v1);
                    *(uint4*)((__half*)Cout + hrow*64 + d) = make_uint4(H0.x,H0.y,H1.x,H1.y);
                } else if (sec == 1) {
                    uint2 H0 = cvt4_h(v0), H1 = cvt4_h(v1);
                    *(uint4*)((__half*)aux1 + hrow*64 + d) = make_uint4(H0.x,H0.y,H1.x,H1.y);
                } else {
                    uint2 H0 = cvt4_h(v0), H1 = cvt4_h(v1);
                    *(uint4*)((__half*)aux2 + hrow*64 + d) = make_uint4(H0.x,H0.y,H1.x,H1.y);
                }
            } else {
                float* C = (float*)Cout;
                if (EPI == 2) {
                    float4 r0 = *(const float4*)&res[grow*N + gcol];
                    float4 r1 = *(const float4*)&res[grow*N + gcol + 4];
                    v0.x += r0.x; v0.y += r0.y; v0.z += r0.z; v0.w += r0.w;
                    v1.x += r1.x; v1.y += r1.y; v1.z += r1.z; v1.w += r1.w;
                }
                *(float4*)&C[grow*(long)N + gcol]     = v0;
                *(float4*)&C[grow*(long)N + gcol + 4] = v1;
            }
            __syncwarp();
        }
    }
}

#define GSMEM_W256 (GSTAGES*(ASZ + 256*ASTR*2))
#define GSMEM_W128 (GSTAGES*(ASZ + 128*ASTR*2))

// ---------------- LN1 ----------------
__global__ __launch_bounds__(256) void ln1_kernel(
    const float* __restrict__ x, const float* __restrict__ w,
    const float* __restrict__ b, __half* __restrict__ xn)
{
    int warp = threadIdx.x >> 5, lane = threadIdx.x & 31;
    long row = (long)blockIdx.x * 8 + warp;
    const float* xr = x + row * Dd;
    float4 v[4];
    float s = 0.f, sq = 0.f;
#pragma unroll
    for (int i = 0; i < 4; i++) {
        v[i] = *(const float4*)&xr[lane*4 + i*128];
        s  += v[i].x + v[i].y + v[i].z + v[i].w;
        sq += v[i].x*v[i].x + v[i].y*v[i].y + v[i].z*v[i].z + v[i].w*v[i].w;
    }
#pragma unroll
    for (int o = 16; o; o >>= 1) {
        s  += __shfl_xor_sync(0xffffffffu, s,  o);
        sq += __shfl_xor_sync(0xffffffffu, sq, o);
    }
    float mean = s * (1.0f/512.0f);
    float var  = sq * (1.0f/512.0f) - mean*mean;
    float rr   = rsqrtf(var + 1e-5f);
    __half* yr = xn + row * Dd;
#pragma unroll
    for (int i = 0; i < 4; i++) {
        int d = lane*4 + i*128;
        float4 wv = *(const float4*)&w[d];
        float4 bv = *(const float4*)&b[d];
        float4 o4;
        o4.x = (v[i].x - mean)*rr*wv.x + bv.x;
        o4.y = (v[i].y - mean)*rr*wv.y + bv.y;
        o4.z = (v[i].z - mean)*rr*wv.z + bv.z;
        o4.w = (v[i].w - mean)*rr*wv.w + bv.w;
        *(uint2*)&yr[d] = cvt4_h(o4);
    }
}

// ---------------- flash attention: 128-q tiles, 256 threads, round-11 pipeline ----------------
#define QSTR 72
#define KBUF (64*QSTR)
#define QBUF (128*QSTR)
#define ATTN_SMEM ((QBUF + 4*KBUF)*2)   // 55296 B

__global__ __launch_bounds__(256) void attn_mma_kernel(
    const __half* __restrict__ Qb, const __half* __restrict__ Kb,
    const __half* __restrict__ Vb, __half* __restrict__ ctx)
{
    extern __shared__ __half smh[];
    __half* Qs  = smh;
    __half* Ks0 = smh + QBUF;
    __half* Vs0 = smh + QBUF + 2*KBUF;

    int b = blockIdx.z, h = blockIdx.y, qt = blockIdx.x;
    int tid = threadIdx.x, wq = tid >> 5, lane = tid & 31;
    long hbase = ((long)b*Hh + h)*Tt;

    const __half* Qg = Qb + (hbase + qt*128)*64;
    const __half* Kg = Kb + hbase*64;
    const __half* Vg = Vb + hbase*64;

    // Q loader: 2 threads per row over 128 rows, 32 halves each
    int qr = tid >> 1, qc = (tid & 1) * 32;
    uint32_t QsA = smem_u32(Qs) + qr*(QSTR*2) + qc*2;
    // K/V loader: 4 threads per row over 64 rows, 16 halves each
    int lr = tid >> 2, lc = (tid & 3) * 16;
    uint32_t KsA = smem_u32(Ks0) + lr*(QSTR*2) + lc*2;
    uint32_t VsA = smem_u32(Vs0) + lr*(QSTR*2) + lc*2;

#pragma unroll
    for (int i = 0; i < 4; i++)
        cp16(QsA + i*16, Qg + qr*64 + qc + i*8);
#define ISSUE_KV(kt, buf) do { \
        const __half* kg_ = Kg + (long)((kt)*64 + lr)*64 + lc; \
        uint32_t kd_ = KsA + (buf)*(KBUF*2); \
        cp16(kd_,      kg_); \
        cp16(kd_ + 16, kg_ + 8); \
        const __half* vg_ = Vg + (long)((kt)*64 + lr)*64 + lc; \
        uint32_t vd_ = VsA + (buf)*(KBUF*2); \
        cp16(vd_,      vg_); \
        cp16(vd_ + 16, vg_ + 8); \
    } while (0)
    ISSUE_KV(0, 0);
    cp_commit();

    float cf[8][4];
#pragma unroll
    for (int j = 0; j < 8; j++) { cf[j][0]=0.f; cf[j][1]=0.f; cf[j][2]=0.f; cf[j][3]=0.f; }
    float m0 = -1e30f, m1 = -1e30f, l0 = 0.f, l1 = 0.f;

    uint32_t qaddr = smem_u32(&Qs[(16*wq + (lane & 15))*QSTR + 8*(lane >> 4)]);

    for (int kt = 0; kt < 16; kt++) {
        if (kt + 1 < 16) ISSUE_KV(kt + 1, (kt + 1) & 1);
        cp_commit();
        cp_wait<1>();
        __syncthreads();
        const __half* Kbuf = Ks0 + (kt & 1)*KBUF;
        const __half* Vbuf = Vs0 + (kt & 1)*KBUF;

        float sf[8][4] = {};
#pragma unroll
        for (int kc = 0; kc < 4; kc++) {
            uint32_t a0, a1, a2, a3;
            ldsm_x4(a0, a1, a2, a3, qaddr + kc*32);
#pragma unroll
            for (int n8 = 0; n8 < 8; n8++) {
                uint32_t b0, b1;
                uint32_t ka = smem_u32(&Kbuf[(8*n8 + (lane & 7))*QSTR + 16*kc + 8*((lane >> 3) & 1)]);
                ldsm_x2(b0, b1, ka);
                mma16816h(sf[n8], a0, a1, a2, a3, b0, b1);
            }
        }

        float mt0 = -1e30f, mt1 = -1e30f;
#pragma unroll
        for (int j = 0; j < 8; j++) {
            mt0 = fmaxf(mt0, fmaxf(sf[j][0], sf[j][1]));
            mt1 = fmaxf(mt1, fmaxf(sf[j][2], sf[j][3]));
        }
        mt0 = fmaxf(mt0, __shfl_xor_sync(0xffffffffu, mt0, 1));
        mt0 = fmaxf(mt0, __shfl_xor_sync(0xffffffffu, mt0, 2));
        mt1 = fmaxf(mt1, __shfl_xor_sync(0xffffffffu, mt1, 1));
        mt1 = fmaxf(mt1, __shfl_xor_sync(0xffffffffu, mt1, 2));
        float mn0 = fmaxf(m0, mt0), mn1 = fmaxf(m1, mt1);
        float cr0 = __expf(m0 - mn0), cr1 = __expf(m1 - mn1);
        m0 = mn0; m1 = mn1; l0 *= cr0; l1 *= cr1;
#pragma unroll
        for (int j = 0; j < 8; j++) {
            cf[j][0] *= cr0; cf[j][1] *= cr0; cf[j][2] *= cr1; cf[j][3] *= cr1;
        }

        uint32_t pa[4][4];
#pragma unroll
        for (int jk = 0; jk < 4; jk++) {
            float e00 = __expf(sf[2*jk][0]   - mn0), e01 = __expf(sf[2*jk][1]   - mn0);
            float e10 = __expf(sf[2*jk][2]   - mn1), e11 = __expf(sf[2*jk][3]   - mn1);
            float e20 = __expf(sf[2*jk+1][0] - mn0), e21 = __expf(sf[2*jk+1][1] - mn0);
            float e30 = __expf(sf[2*jk+1][2] - mn1), e31 = __expf(sf[2*jk+1][3] - mn1);
            l0 += e00 + e01 + e20 + e21;
            l1 += e10 + e11 + e30 + e31;
            __half2 t;
            t = __floats2half2_rn(e00, e01); pa[jk][0] = *(unsigned*)&t;
            t = __floats2half2_rn(e10, e11); pa[jk][1] = *(unsigned*)&t;
            t = __floats2half2_rn(e20, e21); pa[jk][2] = *(unsigned*)&t;
            t = __floats2half2_rn(e30, e31); pa[jk][3] = *(unsigned*)&t;
        }

#pragma unroll
        for (int jk = 0; jk < 4; jk++) {
#pragma unroll
            for (int jd = 0; jd < 8; jd++) {
                uint32_t b0, b1;
                uint32_t va = smem_u32(&Vbuf[(16*jk + (lane & 15))*QSTR + 8*jd]);
                ldsm_x2t(b0, b1, va);
                mma16816h(cf[jd], pa[jk][0], pa[jk][1], pa[jk][2], pa[jk][3], b0, b1);
            }
        }
        __syncthreads();
    }
#undef ISSUE_KV

    l0 += __shfl_xor_sync(0xffffffffu, l0, 1);
    l0 += __shfl_xor_sync(0xffffffffu, l0, 2);
    l1 += __shfl_xor_sync(0xffffffffu, l1, 1);
    l1 += __shfl_xor_sync(0xffffffffu, l1, 2);
    float inv0 = 1.0f / l0, inv1 = 1.0f / l1;

    long grow0 = (long)b*Tt + qt*128 + 16*wq + (lane >> 2);
    long grow1 = grow0 + 8;
    int colb = h*HD + 2*(lane & 3);
    __half* cr0p = ctx + grow0 * Dd;
    __half* cr1p = ctx + grow1 * Dd;
#pragma unroll
    for (int jd = 0; jd < 8; jd++) {
        int col = colb + 8*jd;
        {
            __half2 Hp = __floats2half2_rn(cf[jd][0]*inv0, cf[jd][1]*inv0);
            *(unsigned*)&cr0p[col] = *(unsigned*)&Hp;
        }
        {
            __half2 Hp = __floats2half2_rn(cf[jd][2]*inv1, cf[jd][3]*inv1);
            *(unsigned*)&cr1p[col] = *(unsigned*)&Hp;
        }
    }
}

// ---------------- separable Gaussian position attention ----------------
__global__ __launch_bounds__(256) void av_init_kernel(float* __restrict__ Av) {
    int i = blockIdx.x * 256 + threadIdx.x;
    float d = (float)((i >> 6) - (i & 63));
    Av[i] = __expf(-d * d * (1.0f/512.0f));
}

__global__ __launch_bounds__(256) void scatter_kernel(
    const __half* __restrict__ xn, const int* __restrict__ posv,
    const int* __restrict__ posh, float* __restrict__ G, float* __restrict__ cnt)
{
    int warp = threadIdx.x >> 5, lane = threadIdx.x & 31;
    long row = (long)blockIdx.x * 8 + warp;
    int b = (int)(row >> 10), t = (int)(row & 1023);
    int pv = posv[b*Tt + t], ph = posh[b*Tt + t];
    float* dst = G + (((long)b*64 + pv)*64 + ph) * 512;
    const __half* ar = xn + row * Dd;
#pragma unroll
    for (int i = 0; i < 16; i++) {
        int d = i*32 + lane;
        atomicAdd(&dst[d], __half2float(ar[d]));
    }
    if (lane == 0) atomicAdd(&cnt[((long)b*64 + pv)*64 + ph], 1.0f);
}

__global__ __launch_bounds__(512) void gconv_kernel(
    const float* __restrict__ in, float* __restrict__ out,
    const float* __restrict__ Av, int stride_fix, int stride_c)
{
    __shared__ float AsT[64][64];
    int fix = blockIdx.x, b = blockIdx.y, tid = threadIdx.x;
    for (int i = tid; i < 4096; i += 512)
        AsT[i & 63][i >> 6] = Av[i];
    __syncthreads();
    const float* ib = in  + (long)b*2097152 + (long)fix*stride_fix + tid;
    float* ob       = out + (long)b*2097152 + (long)fix*stride_fix + tid;
    float acc[64];
#pragma unroll
    for (int v = 0; v < 64; v++) acc[v] = 0.f;
    for (int c = 0; c < 64; c++) {
        float g = ib[(long)c * stride_c];
#pragma unroll
        for (int v4 = 0; v4 < 16; v4++) {
            float4 a4 = *(const float4*)&AsT[c][v4*4];
            acc[v4*4+0] += a4.x*g; acc[v4*4+1] += a4.y*g;
            acc[v4*4+2] += a4.z*g; acc[v4*4+3] += a4.w*g;
        }
    }
#pragma unroll
    for (int v = 0; v < 64; v++) ob[(long)v * stride_c] = acc[v];
}

__global__ __launch_bounds__(1024) void dcnt_kernel(
    const float* __restrict__ cnt, const float* __restrict__ Av,
    float* __restrict__ dcnt)
{
    __shared__ float sc[4096], st[4096];
    int b = blockIdx.x, tid = threadIdx.x;
    for (int i = tid; i < 4096; i += 1024) sc[i] = cnt[(long)b*4096 + i];
    __syncthreads();
    for (int i = tid; i < 4096; i += 1024) {
        int v = i >> 6, hp = i & 63;
        float s = 0.f;
        for (int vp = 0; vp < 64; vp++) s += Av[v*64+vp] * sc[vp*64+hp];
        st[i] = s;
    }
    __syncthreads();
    for (int i = tid; i < 4096; i += 1024) {
        int v = i >> 6, h = i & 63;
        float s = 0.f;
        for (int hp = 0; hp < 64; hp++) s += Av[h*64+hp] * st[v*64+hp];
        dcnt[(long)b*4096 + i] = 1.0f / s;
    }
}

// ---------------- combine + LN2 (stdo fp16) ----------------
__global__ __launch_bounds__(256) void combine_ln2_kernel(
    const float* __restrict__ x, const __half* __restrict__ stdo,
    const float* __restrict__ O, const float* __restrict__ dcntInv,
    const int* __restrict__ posv, const int* __restrict__ posh,
    const float* __restrict__ gate,
    const float* __restrict__ w, const float* __restrict__ bb,
    float* __restrict__ x1, __half* __restrict__ xn2)
{
    int warp = threadIdx.x >> 5, lane = threadIdx.x & 31;
    long row = (long)blockIdx.x * 8 + warp;
    int b = (int)(row >> 10), t = (int)(row & 1023);
    int pv = posv[b*Tt + t], ph = posh[b*Tt + t];
    float g = 1.0f / (1.0f + __expf(-gate[0]));
    float gi = 1.0f - g;
    float inv_ks = dcntInv[((long)b*64 + pv)*64 + ph];
    const float* korow = O + (((long)b*64 + pv)*64 + ph) * 512;
    long base = row * Dd;
    float4 v[4];
    float s = 0.f, sq = 0.f;
#pragma unroll
    for (int i = 0; i < 4; i++) {
        int d = lane*4 + i*128;
        float4 xv = *(const float4*)&x[base + d];
        uint2 su = *(const uint2*)&stdo[base + d];
        float2 s01 = __half22float2(*(const __half2*)&su.x);
        float2 s23 = __half22float2(*(const __half2*)&su.y);
        float4 kv = *(const float4*)&korow[d];
        float4 o4;
        o4.x = xv.x + g*s01.x + gi*kv.x*inv_ks;
        o4.y = xv.y + g*s01.y + gi*kv.y*inv_ks;
        o4.z = xv.z + g*s23.x + gi*kv.z*inv_ks;
        o4.w = xv.w + g*s23.y + gi*kv.w*inv_ks;
        *(float4*)&x1[base + d] = o4;
        v[i] = o4;
        s  += o4.x + o4.y + o4.z + o4.w;
        sq += o4.x*o4.x + o4.y*o4.y + o4.z*o4.z + o4.w*o4.w;
    }
#pragma unroll
    for (int o = 16; o; o >>= 1) {
        s  += __shfl_xor_sync(0xffffffffu, s,  o);
        sq += __shfl_xor_sync(0xffffffffu, sq, o);
    }
    float mean = s * (1.0f/512.0f);
    float var  = sq * (1.0f/512.0f) - mean*mean;
    float rr   = rsqrtf(var + 1e-5f);
    __half* arow = xn2 + row * Dd;
#pragma unroll
    for (int i = 0; i < 4; i++) {
        int d = lane*4 + i*128;
        float4 wv = *(const float4*)&w[d];
        float4 bv = *(const float4*)&bb[d];
        float4 o4;
        o4.x = (v[i].x - mean)*rr*wv.x + bv.x;
        o4.y = (v[i].y - mean)*rr*wv.y + bv.y;
        o4.z = (v[i].z - mean)*rr*wv.z + bv.z;
        o4.w = (v[i].w - mean)*rr*wv.w + bv.w;
        *(uint2*)&arow[d] = cvt4_h(o4);
    }
}

// ---------------- launch (round-11 stream structure) ----------------
extern "C" void kernel_launch(void* const* d_in, const int* in_sizes, int n_in,
                              void* d_out, int out_size)
{
    const float* x      = (const float*)d_in[0];
    const int*   posv   = (const int*)  d_in[1];
    const int*   posh   = (const int*)  d_in[2];
    const float* n1w    = (const float*)d_in[3];
    const float* n1b    = (const float*)d_in[4];
    const float* in_w   = (const float*)d_in[5];
    const float* in_b   = (const float*)d_in[6];
    const float* out_w  = (const float*)d_in[7];
    const float* out_b  = (const float*)d_in[8];
    const float* n2w    = (const float*)d_in[9];
    const float* n2b    = (const float*)d_in[10];
    const float* w1     = (const float*)d_in[11];
    const float* b1     = (const float*)d_in[12];
    const float* w2     = (const float*)d_in[13];
    const float* b2     = (const float*)d_in[14];
    const float* gate   = (const float*)d_in[15];
    float* out = (float*)d_out;

    __half *xn, *ctx, *stdo, *xn2, *hB, *wIN, *wOUT, *w1p, *w2p, *Qbp, *Kbp, *Vbp;
    float *G, *T1, *cnt, *dcnt, *Av, *x1;
    cudaGetSymbolAddress((void**)&xn,   g_xn);
    cudaGetSymbolAddress((void**)&Qbp,  g_Qb);
    cudaGetSymbolAddress((void**)&Kbp,  g_Kb);
    cudaGetSymbolAddress((void**)&Vbp,  g_Vb);
    cudaGetSymbolAddress((void**)&ctx,  g_ctx);
    cudaGetSymbolAddress((void**)&stdo, g_stdo);
    cudaGetSymbolAddress((void**)&G,    g_G);
    cudaGetSymbolAddress((void**)&T1,   g_T1);
    cudaGetSymbolAddress((void**)&cnt,  g_cnt);
    cudaGetSymbolAddress((void**)&dcnt, g_dcnt);
    cudaGetSymbolAddress((void**)&Av,   g_Av);
    cudaGetSymbolAddress((void**)&x1,   g_x1);
    cudaGetSymbolAddress((void**)&xn2,  g_xn2);
    cudaGetSymbolAddress((void**)&hB,   g_hB);
    cudaGetSymbolAddress((void**)&wIN,  g_wIN);
    cudaGetSymbolAddress((void**)&wOUT, g_wOUT);
    cudaGetSymbolAddress((void**)&w1p,  g_w1);
    cudaGetSymbolAddress((void**)&w2p,  g_w2);

    cudaFuncSetAttribute(gemm_fp16<256,3>, cudaFuncAttributeMaxDynamicSharedMemorySize, GSMEM_W256);
    cudaFuncSetAttribute(gemm_fp16<256,1>, cudaFuncAttributeMaxDynamicSharedMemorySize, GSMEM_W256);
    cudaFuncSetAttribute(gemm_fp16<128,4>, cudaFuncAttributeMaxDynamicSharedMemorySize, GSMEM_W128);
    cudaFuncSetAttribute(gemm_fp16<128,2>, cudaFuncAttributeMaxDynamicSharedMemorySize, GSMEM_W128);
    cudaFuncSetAttribute(attn_mma_kernel,  cudaFuncAttributeMaxDynamicSharedMemorySize, ATTN_SMEM);

    // side stream fork (round-11 structure)
    cudaStream_t sA;
    cudaStreamCreateWithFlags(&sA, cudaStreamNonBlocking);
    cudaEvent_t evRoot, evW, evLN, evG;
    cudaEventCreateWithFlags(&evRoot, cudaEventDisableTiming);
    cudaEventCreateWithFlags(&evW,   cudaEventDisableTiming);
    cudaEventCreateWithFlags(&evLN,  cudaEventDisableTiming);
    cudaEventCreateWithFlags(&evG,   cudaEventDisableTiming);

    cudaEventRecord(evRoot, 0);
    cudaStreamWaitEvent(sA, evRoot, 0);

    // side: weight conversions (out/w1/w2), Av, zeros
    conv_w_kernel<<<(Dd*Dd/4 + 255)/256, 256, 0, sA>>>(out_w, wOUT, Dd*Dd/4);
    conv_w_kernel<<<(D4*Dd/4 + 255)/256, 256, 0, sA>>>(w1,    w1p,  D4*Dd/4);
    conv_w_kernel<<<(Dd*D4/4 + 255)/256, 256, 0, sA>>>(w2,    w2p,  Dd*D4/4);
    cudaEventRecord(evW, sA);
    av_init_kernel<<<16, 256, 0, sA>>>(Av);
    zero_kernel<<<(Bb*4096*512/4 + 255)/256, 256, 0, sA>>>(G, Bb*4096*512/4);
    zero_kernel<<<(Bb*4096/4 + 255)/256, 256, 0, sA>>>(cnt, Bb*4096/4);

    // main: conv wIN, LN1
    conv_w_kernel<<<(3*Dd*Dd/4 + 255)/256, 256>>>(in_w, wIN, 3*Dd*Dd/4);
    ln1_kernel<<<ROWS/8, 256>>>(x, n1w, n1b, xn);
    cudaEventRecord(evLN, 0);

    // side: Gaussian path
    cudaStreamWaitEvent(sA, evLN, 0);
    scatter_kernel<<<ROWS/8, 256, 0, sA>>>(xn, posv, posh, G, cnt);
    gconv_kernel<<<dim3(64, Bb), 512, 0, sA>>>(G, T1, Av, 512, 64*512);
    gconv_kernel<<<dim3(64, Bb), 512, 0, sA>>>(T1, G, Av, 64*512, 512);
    dcnt_kernel<<<Bb, 1024, 0, sA>>>(cnt, Av, dcnt);
    cudaEventRecord(evG, sA);

    // main: QKV GEMM
    gemm_fp16<256, 3><<<dim3(6, 64), 256, GSMEM_W256>>>(
        xn, wIN, in_b, nullptr, Qbp, Kbp, Vbp, 3*Dd, Dd);

    // main: attention (128-q tiles)
    attn_mma_kernel<<<dim3(Tt/128, Hh, Bb), 256, ATTN_SMEM>>>(Qbp, Kbp, Vbp, ctx);

    // main: out-proj -> fp16 stdo
    cudaStreamWaitEvent(0, evW, 0);
    gemm_fp16<128, 4><<<dim3(4, 64), 256, GSMEM_W128>>>(
        ctx, wOUT, out_b, nullptr, stdo, nullptr, nullptr, Dd, Dd);

    // main: combine + LN2
    cudaStreamWaitEvent(0, evG, 0);
    combine_ln2_kernel<<<ROWS/8, 256>>>(
        x, stdo, G, dcnt, posv, posh, gate, n2w, n2b, x1, xn2);

    // main: MLP
    gemm_fp16<256, 1><<<dim3(8, 64), 256, GSMEM_W256>>>(
        xn2, w1p, b1, nullptr, hB, nullptr, nullptr, D4, Dd);
    gemm_fp16<128, 2><<<dim3(4, 64), 256, GSMEM_W128>>>(
        hB, w2p, b2, x1, out, nullptr, nullptr, Dd, D4);
}